// round 8
// baseline (speedup 1.0000x reference)
#include <cuda_runtime.h>
#include <cuda_bf16.h>
#include <math.h>

// Problem constants (fixed instance)
#define T_TOK   16384
#define C_DIM   1024
#define H_HEADS 16
#define HDIM    64
#define NSEG    32
#define SEGLEN  512

// Scratch (allocation-free: __device__ globals)
__device__ float g_qkv[(size_t)T_TOK * 3 * C_DIM];   // [T, 3C]
__device__ float g_y[(size_t)T_TOK * C_DIM];         // [T, C]

__device__ __forceinline__ unsigned f2tf32(float x) {
    unsigned u;
    asm("cvt.rna.tf32.f32 %0, %1;" : "=r"(u) : "f"(x));
    return u;
}
__device__ __forceinline__ float tf32f(float x) { return __uint_as_float(f2tf32(x)); }

__device__ __forceinline__ void mma_tf32(float* c, const unsigned* a,
                                         unsigned b0, unsigned b1) {
    asm volatile(
        "mma.sync.aligned.m16n8k8.row.col.f32.tf32.tf32.f32 "
        "{%0,%1,%2,%3}, {%4,%5,%6,%7}, {%8,%9}, {%0,%1,%2,%3};"
        : "+f"(c[0]), "+f"(c[1]), "+f"(c[2]), "+f"(c[3])
        : "r"(a[0]), "r"(a[1]), "r"(a[2]), "r"(a[3]), "r"(b0), "r"(b1));
}

// ---------------------------------------------------------------------------
// TF32 GEMM v2: C[M,N] = A[M,K] * B[K,N], row-major.
// Block tile 128(M) x 256(N), BK=16, 8 warps (2m x 4n), warp tile 64x64.
// Smem float2 = (k, k+4) pair, xor swizzle -> conflict-free lds.64 frag loads.
// 32 mma per 16 lds.64 per warp per k8 (2x the arithmetic intensity of v1).
// ---------------------------------------------------------------------------
__global__ __launch_bounds__(256, 1)
void gemm_tf32(const float* __restrict__ A, const float* __restrict__ B,
               float* __restrict__ C, int M, int N, int K)
{
    __shared__ float2 As[2][2][512];    // [buf][kb][m*4 + swz(c)]      16KB
    __shared__ float2 Bs[2][2][1024];   // [buf][kb][n*4 + swz(c)]      32KB

    const int tid  = threadIdx.x;
    const int lane = tid & 31;
    const int w    = tid >> 5;
    const int wm   = (w >> 2) * 64;      // 0 or 64
    const int wn   = (w & 3) * 64;       // 0,64,128,192
    const int bm   = blockIdx.y * 128;
    const int bn   = blockIdx.x * 256;

    const int arow = tid >> 2;           // 0..63
    const int acol = (tid & 3) << 2;     // 0,4,8,12
    const int akb  = acol >> 3;
    const int ah   = (acol >> 2) & 1;
    const int bkk  = tid & 15;           // k row
    const int bng  = tid >> 4;           // 0..15 -> n group of 16
    const int bkb  = bkk >> 3;
    const int bp   = bkk & 3;
    const int bh   = (bkk >> 2) & 1;

    const float* Ap = A + (size_t)bm * K;
    const float* Bp = B + bn;

    float acc[4][8][4];
#pragma unroll
    for (int mt = 0; mt < 4; mt++)
#pragma unroll
        for (int nt = 0; nt < 8; nt++)
#pragma unroll
            for (int i = 0; i < 4; i++) acc[mt][nt][i] = 0.0f;

    const int fr = lane >> 2;
    const int fc = lane & 3;

    // Prefetch first tile
    float4 ra0 = *(const float4*)(Ap + (size_t)arow * K + acol);
    float4 ra1 = *(const float4*)(Ap + (size_t)(arow + 64) * K + acol);
    float4 rb[4];
#pragma unroll
    for (int j = 0; j < 4; j++)
        rb[j] = *(const float4*)(Bp + (size_t)bkk * N + bng * 16 + j * 4);

    int cur = 0;
    for (int k0 = 0; k0 < K; k0 += 16) {
        // ---- store tile into smem[cur] ----
        {
            float av0[4] = {ra0.x, ra0.y, ra0.z, ra0.w};
            float av1[4] = {ra1.x, ra1.y, ra1.z, ra1.w};
            float* a0p = (float*)&As[cur][akb][0];
#pragma unroll
            for (int e = 0; e < 4; e++) {
                a0p[(arow * 4 + (e ^ (arow & 3))) * 2 + ah]        = tf32f(av0[e]);
                a0p[((arow + 64) * 4 + (e ^ (arow & 3))) * 2 + ah] = tf32f(av1[e]);
            }
            float* b0p = (float*)&Bs[cur][bkb][0];
#pragma unroll
            for (int j = 0; j < 4; j++) {
                float bv[4] = {rb[j].x, rb[j].y, rb[j].z, rb[j].w};
#pragma unroll
                for (int e = 0; e < 4; e++) {
                    int n = bng * 16 + j * 4 + e;
                    b0p[(n * 4 + (bp ^ e)) * 2 + bh] = tf32f(bv[e]);
                }
            }
        }
        __syncthreads();

        // ---- prefetch next tile ----
        if (k0 + 16 < K) {
            ra0 = *(const float4*)(Ap + (size_t)arow * K + k0 + 16 + acol);
            ra1 = *(const float4*)(Ap + (size_t)(arow + 64) * K + k0 + 16 + acol);
#pragma unroll
            for (int j = 0; j < 4; j++)
                rb[j] = *(const float4*)(Bp + (size_t)(k0 + 16 + bkk) * N + bng * 16 + j * 4);
        }

        // ---- compute: 2 k8-steps x 32 mma per warp ----
#pragma unroll
        for (int kb = 0; kb < 2; kb++) {
            const float2* Ak = As[cur][kb];
            const float2* Bk = Bs[cur][kb];

            unsigned af[4][4];
#pragma unroll
            for (int mt = 0; mt < 4; mt++) {
                int row = wm + mt * 16 + fr;
                float2 lo = Ak[row * 4 + (fc ^ (row & 3))];
                float2 hi = Ak[(row + 8) * 4 + (fc ^ (row & 3))];
                af[mt][0] = __float_as_uint(lo.x);
                af[mt][1] = __float_as_uint(hi.x);
                af[mt][2] = __float_as_uint(lo.y);
                af[mt][3] = __float_as_uint(hi.y);
            }
#pragma unroll
            for (int nt = 0; nt < 8; nt++) {
                int n = wn + nt * 8 + fr;
                float2 bb = Bk[n * 4 + (fc ^ (n & 3))];
                unsigned b0 = __float_as_uint(bb.x);
                unsigned b1 = __float_as_uint(bb.y);
#pragma unroll
                for (int mt = 0; mt < 4; mt++)
                    mma_tf32(acc[mt][nt], af[mt], b0, b1);
            }
        }
        cur ^= 1;
    }

    // ---- epilogue ----
#pragma unroll
    for (int mt = 0; mt < 4; mt++) {
#pragma unroll
        for (int nt = 0; nt < 8; nt++) {
            int row = bm + wm + mt * 16 + fr;
            int col = bn + wn + nt * 8 + 2 * fc;
            *(float2*)&C[(size_t)row * N + col] =
                make_float2(acc[mt][nt][0], acc[mt][nt][1]);
            *(float2*)&C[(size_t)(row + 8) * N + col] =
                make_float2(acc[mt][nt][2], acc[mt][nt][3]);
        }
    }
}

// ---------------------------------------------------------------------------
// Tensor-core block-diagonal attention (tf32), flash-style online softmax.
// Block = 128 threads (4 warps), 64 queries of one (head, segment).
// Each warp owns 16 query rows -> softmax is warp-local (shfl over fc only).
// k-permuted pair layout: smem float2 = (k=2c, k=2c+1) so S-accumulator pairs
// map directly onto A-operand lds.64 for the PV mma (V stored key-pair-major).
// Smem: Ks 16KB + Vs 16KB + Ps(/Q staging) 16KB = 48KB.
// ---------------------------------------------------------------------------
__global__ __launch_bounds__(128, 3)
void attn_tc(const float* __restrict__ qkv, float* __restrict__ y)
{
    __shared__ float2 Ks[8][256];   // [kb][key*4 + (c ^ (key&3))] = (K[key][kb*8+2c], ..+2c+1)
    __shared__ float2 Vs[8][256];   // [kb][d*4   + (c ^ (d&3))]   = (V[kb*8+2c][d], V[kb*8+2c+1][d])
    __shared__ float2 Ps[8][256];   // [kb][row*4 + (c ^ (row&3))] = (P[row][kb*8+2c], ..+2c+1)

    const int tid  = threadIdx.x;
    const int lane = tid & 31;
    const int w    = tid >> 5;       // 0..3
    const int fr   = lane >> 2;      // 0..7
    const int fc   = lane & 3;       // 0..3
    const int h    = blockIdx.x & (H_HEADS - 1);
    const int seg  = blockIdx.x >> 4;
    const int q0   = seg * SEGLEN + blockIdx.y * 64;
    const int r0   = w * 16 + fr;    // warp-local q row (c0/c1); r0+8 for c2/c3
    const int sw   = fc ^ (fr & 3);

    const float* qb = qkv + (size_t)q0 * (3 * C_DIM) + h * HDIM;

    // ---- stage Q (scaled by 1/8, tf32) into Ps ----
    {
        const int row = tid >> 1;            // 0..63
        const int d0  = (tid & 1) * 32;
        const float* qr = qb + (size_t)row * (3 * C_DIM);
#pragma unroll
        for (int j = 0; j < 8; j++) {
            int d = d0 + j * 4;
            float4 v = *(const float4*)(qr + d);
            int kb = d >> 3;
            int cr = (d & 7) >> 1;           // 0 or 2
            Ps[kb][row * 4 + (cr ^ (row & 3))] =
                make_float2(tf32f(v.x * 0.125f), tf32f(v.y * 0.125f));
            Ps[kb][row * 4 + ((cr + 1) ^ (row & 3))] =
                make_float2(tf32f(v.z * 0.125f), tf32f(v.w * 0.125f));
        }
    }
    __syncthreads();

    // ---- Q fragments -> registers (held for whole kernel) ----
    unsigned qf[8][4];
#pragma unroll
    for (int kb = 0; kb < 8; kb++) {
        float2 lo = Ps[kb][r0 * 4 + sw];
        float2 hi = Ps[kb][(r0 + 8) * 4 + sw];
        qf[kb][0] = __float_as_uint(lo.x);
        qf[kb][1] = __float_as_uint(hi.x);
        qf[kb][2] = __float_as_uint(lo.y);
        qf[kb][3] = __float_as_uint(hi.y);
    }

    float O[8][4];
#pragma unroll
    for (int nt = 0; nt < 8; nt++)
#pragma unroll
        for (int i = 0; i < 4; i++) O[nt][i] = 0.0f;
    float m0 = -1e30f, m1 = -1e30f, l0 = 0.0f, l1 = 0.0f;

    for (int kc = 0; kc < 8; kc++) {
        const float* kbase = qkv + (size_t)(seg * SEGLEN + kc * 64) * (3 * C_DIM)
                             + C_DIM + h * HDIM;
        const float* vbase = kbase + C_DIM;

        __syncthreads();   // all warps done reading Ks/Vs of previous chunk
        // ---- load K chunk ----
        {
            const int key = tid >> 1;
            const int d0  = (tid & 1) * 32;
            const float* kr = kbase + (size_t)key * (3 * C_DIM);
#pragma unroll
            for (int j = 0; j < 8; j++) {
                int d = d0 + j * 4;
                float4 v = *(const float4*)(kr + d);
                int kb = d >> 3;
                int cr = (d & 7) >> 1;
                Ks[kb][key * 4 + (cr ^ (key & 3))] =
                    make_float2(tf32f(v.x), tf32f(v.y));
                Ks[kb][key * 4 + ((cr + 1) ^ (key & 3))] =
                    make_float2(tf32f(v.z), tf32f(v.w));
            }
        }
        // ---- load V chunk (key-pair-major transposed layout) ----
        {
            const int kp = tid >> 2;          // 0..31 -> keys 2kp, 2kp+1
            const int d0 = (tid & 3) * 16;
            const float* vr0 = vbase + (size_t)(2 * kp) * (3 * C_DIM);
            const float* vr1 = vr0 + (3 * C_DIM);
            const int kb = kp >> 2;
            const int cr = kp & 3;
#pragma unroll
            for (int j = 0; j < 4; j++) {
                int d = d0 + j * 4;
                float4 a = *(const float4*)(vr0 + d);
                float4 b = *(const float4*)(vr1 + d);
                Vs[kb][(d + 0) * 4 + (cr ^ ((d + 0) & 3))] = make_float2(tf32f(a.x), tf32f(b.x));
                Vs[kb][(d + 1) * 4 + (cr ^ ((d + 1) & 3))] = make_float2(tf32f(a.y), tf32f(b.y));
                Vs[kb][(d + 2) * 4 + (cr ^ ((d + 2) & 3))] = make_float2(tf32f(a.z), tf32f(b.z));
                Vs[kb][(d + 3) * 4 + (cr ^ ((d + 3) & 3))] = make_float2(tf32f(a.w), tf32f(b.w));
            }
        }
        __syncthreads();

        // ---- S = Q K^T (16 rows x 64 keys per warp) ----
        float s[8][4];
#pragma unroll
        for (int nt = 0; nt < 8; nt++)
#pragma unroll
            for (int i = 0; i < 4; i++) s[nt][i] = 0.0f;

#pragma unroll
        for (int kb = 0; kb < 8; kb++) {
#pragma unroll
            for (int nt = 0; nt < 8; nt++) {
                int n = nt * 8 + fr;
                float2 bb = Ks[kb][n * 4 + (fc ^ (n & 3))];
                mma_tf32(s[nt], qf[kb],
                         __float_as_uint(bb.x), __float_as_uint(bb.y));
            }
        }

        // ---- online softmax (warp-local; rows r0 and r0+8) ----
        float mx0 = -1e30f, mx1 = -1e30f;
#pragma unroll
        for (int nt = 0; nt < 8; nt++) {
            mx0 = fmaxf(mx0, fmaxf(s[nt][0], s[nt][1]));
            mx1 = fmaxf(mx1, fmaxf(s[nt][2], s[nt][3]));
        }
        mx0 = fmaxf(mx0, __shfl_xor_sync(0xffffffffu, mx0, 1));
        mx0 = fmaxf(mx0, __shfl_xor_sync(0xffffffffu, mx0, 2));
        mx1 = fmaxf(mx1, __shfl_xor_sync(0xffffffffu, mx1, 1));
        mx1 = fmaxf(mx1, __shfl_xor_sync(0xffffffffu, mx1, 2));

        float mn0 = fmaxf(m0, mx0), mn1 = fmaxf(m1, mx1);
        float fac0 = __expf(m0 - mn0), fac1 = __expf(m1 - mn1);
        float rs0 = 0.0f, rs1 = 0.0f;
#pragma unroll
        for (int nt = 0; nt < 8; nt++) {
            s[nt][0] = __expf(s[nt][0] - mn0);
            s[nt][1] = __expf(s[nt][1] - mn0);
            s[nt][2] = __expf(s[nt][2] - mn1);
            s[nt][3] = __expf(s[nt][3] - mn1);
            rs0 += s[nt][0] + s[nt][1];
            rs1 += s[nt][2] + s[nt][3];
        }
        rs0 += __shfl_xor_sync(0xffffffffu, rs0, 1);
        rs0 += __shfl_xor_sync(0xffffffffu, rs0, 2);
        rs1 += __shfl_xor_sync(0xffffffffu, rs1, 1);
        rs1 += __shfl_xor_sync(0xffffffffu, rs1, 2);

        l0 = l0 * fac0 + rs0;  m0 = mn0;
        l1 = l1 * fac1 + rs1;  m1 = mn1;
#pragma unroll
        for (int nt = 0; nt < 8; nt++) {
            O[nt][0] *= fac0; O[nt][1] *= fac0;
            O[nt][2] *= fac1; O[nt][3] *= fac1;
        }

        // ---- write P (warp-private rows; no sync needed) ----
#pragma unroll
        for (int nt = 0; nt < 8; nt++) {
            Ps[nt][r0 * 4 + sw]       = make_float2(tf32f(s[nt][0]), tf32f(s[nt][1]));
            Ps[nt][(r0 + 8) * 4 + sw] = make_float2(tf32f(s[nt][2]), tf32f(s[nt][3]));
        }

        // ---- O += P V ----
#pragma unroll
        for (int kb = 0; kb < 8; kb++) {
            float2 lo = Ps[kb][r0 * 4 + sw];
            float2 hi = Ps[kb][(r0 + 8) * 4 + sw];
            unsigned af[4] = {__float_as_uint(lo.x), __float_as_uint(hi.x),
                              __float_as_uint(lo.y), __float_as_uint(hi.y)};
#pragma unroll
            for (int nt = 0; nt < 8; nt++) {
                int n = nt * 8 + fr;
                float2 vv = Vs[kb][n * 4 + (fc ^ (n & 3))];
                mma_tf32(O[nt], af,
                         __float_as_uint(vv.x), __float_as_uint(vv.y));
            }
        }
    }

    // ---- epilogue: normalize, write y [T, C] ----
    const float inv0 = 1.0f / l0, inv1 = 1.0f / l1;
    float* yb = y + (size_t)q0 * C_DIM + h * HDIM;
#pragma unroll
    for (int nt = 0; nt < 8; nt++) {
        int col = nt * 8 + 2 * fc;
        *(float2*)&yb[(size_t)r0 * C_DIM + col] =
            make_float2(O[nt][0] * inv0, O[nt][1] * inv0);
        *(float2*)&yb[(size_t)(r0 + 8) * C_DIM + col] =
            make_float2(O[nt][2] * inv1, O[nt][3] * inv1);
    }
}

// ---------------------------------------------------------------------------
extern "C" void kernel_launch(void* const* d_in, const int* in_sizes, int n_in,
                              void* d_out, int out_size)
{
    const float* x      = (const float*)d_in[0];
    const float* w_attn = (const float*)d_in[1];
    const float* w_proj = (const float*)d_in[2];
    float* out = (float*)d_out;

    void* qkv_p = nullptr;
    void* y_p   = nullptr;
    cudaGetSymbolAddress(&qkv_p, g_qkv);
    cudaGetSymbolAddress(&y_p,   g_y);
    float* qkv = (float*)qkv_p;
    float* y   = (float*)y_p;

    // 1) qkv = x @ w_attn   [16384,1024] x [1024,3072]
    gemm_tf32<<<dim3(3 * C_DIM / 256, T_TOK / 128), 256>>>(x, w_attn, qkv,
                                                           T_TOK, 3 * C_DIM, C_DIM);
    // 2) block-diagonal attention -> y [T, C]  (tensor cores)
    attn_tc<<<dim3(H_HEADS * NSEG, SEGLEN / 64), 128>>>(qkv, y);

    // 3) out = y @ w_proj   [16384,1024] x [1024,1024]
    gemm_tf32<<<dim3(C_DIM / 256, T_TOK / 128), 256>>>(y, w_proj, out,
                                                       T_TOK, C_DIM, C_DIM);
}

// round 9
// speedup vs baseline: 1.9607x; 1.9607x over previous
#include <cuda_runtime.h>
#include <cuda_bf16.h>
#include <math.h>

// Problem constants (fixed instance)
#define T_TOK   16384
#define C_DIM   1024
#define H_HEADS 16
#define HDIM    64
#define NSEG    32
#define SEGLEN  512

// Scratch (allocation-free: __device__ globals)
__device__ float g_qkv[(size_t)T_TOK * 3 * C_DIM];   // [T, 3C]
__device__ float g_y[(size_t)T_TOK * C_DIM];         // [T, C]

__device__ __forceinline__ unsigned f2tf32(float x) {
    unsigned u;
    asm("cvt.rna.tf32.f32 %0, %1;" : "=r"(u) : "f"(x));
    return u;
}
__device__ __forceinline__ float tf32f(float x) { return __uint_as_float(f2tf32(x)); }

__device__ __forceinline__ void mma_tf32(float* c, const unsigned* a,
                                         unsigned b0, unsigned b1) {
    asm volatile(
        "mma.sync.aligned.m16n8k8.row.col.f32.tf32.tf32.f32 "
        "{%0,%1,%2,%3}, {%4,%5,%6,%7}, {%8,%9}, {%0,%1,%2,%3};"
        : "+f"(c[0]), "+f"(c[1]), "+f"(c[2]), "+f"(c[3])
        : "r"(a[0]), "r"(a[1]), "r"(a[2]), "r"(a[3]), "r"(b0), "r"(b1));
}

// ---------------------------------------------------------------------------
// TF32 GEMM (proven v1): C[M,N] = A[M,K] * B[K,N], row-major.
// 128x128 block tile, BK=16, 256 threads = 8 warps (2m x 4n), warp tile 64x32.
// 120 regs -> 2 CTAs/SM (16 warps). Measured: tensor=34%, QKV=992us.
// ---------------------------------------------------------------------------
#define KBPAD 516   // 128*4 float2 slots + 4 pad

__global__ __launch_bounds__(256, 2)
void gemm_tf32(const float* __restrict__ A, const float* __restrict__ B,
               float* __restrict__ C, int M, int N, int K)
{
    __shared__ float2 As[2][2][KBPAD];   // [buf][kb][m*4 + swz(c)]
    __shared__ float2 Bs[2][2][KBPAD];   // [buf][kb][n*4 + swz(c)]

    const int tid  = threadIdx.x;
    const int lane = tid & 31;
    const int w    = tid >> 5;
    const int wm   = (w >> 2) * 64;      // warp M offset (0 or 64)
    const int wn   = (w & 3) * 32;       // warp N offset
    const int bm   = blockIdx.y * 128;
    const int bn   = blockIdx.x * 128;

    const int arow = tid >> 2;            // 0..63
    const int acol = (tid & 3) << 2;      // 0,4,8,12
    const int akb  = acol >> 3;
    const int ah   = (acol >> 2) & 1;
    const int bkk  = tid & 15;
    const int bng  = tid >> 4;
    const int bkb  = bkk >> 3;
    const int bp   = bkk & 3;
    const int bh   = (bkk >> 2) & 1;

    const float* Ap = A + (size_t)bm * K;
    const float* Bp = B + bn;

    float acc[4][4][4];
#pragma unroll
    for (int mt = 0; mt < 4; mt++)
#pragma unroll
        for (int nt = 0; nt < 4; nt++)
#pragma unroll
            for (int i = 0; i < 4; i++) acc[mt][nt][i] = 0.0f;

    const int fr = lane >> 2;
    const int fc = lane & 3;

    float4 ra0 = *(const float4*)(Ap + (size_t)arow * K + acol);
    float4 ra1 = *(const float4*)(Ap + (size_t)(arow + 64) * K + acol);
    float4 rb0 = *(const float4*)(Bp + (size_t)bkk * N + bng * 8);
    float4 rb1 = *(const float4*)(Bp + (size_t)bkk * N + bng * 8 + 4);

    int cur = 0;
    for (int k0 = 0; k0 < K; k0 += 16) {
        {
            float av0[4] = {ra0.x, ra0.y, ra0.z, ra0.w};
            float av1[4] = {ra1.x, ra1.y, ra1.z, ra1.w};
            float* a0p = (float*)&As[cur][akb][0];
#pragma unroll
            for (int e = 0; e < 4; e++) {
                a0p[(arow * 4 + (e ^ (arow & 3))) * 2 + ah]        = tf32f(av0[e]);
                a0p[((arow + 64) * 4 + (e ^ (arow & 3))) * 2 + ah] = tf32f(av1[e]);
            }
            float bv0[4] = {rb0.x, rb0.y, rb0.z, rb0.w};
            float bv1[4] = {rb1.x, rb1.y, rb1.z, rb1.w};
            float* b0p = (float*)&Bs[cur][bkb][0];
#pragma unroll
            for (int e = 0; e < 4; e++) {
                int n1 = bng * 8 + e;
                int n2 = bng * 8 + 4 + e;
                b0p[(n1 * 4 + (bp ^ e)) * 2 + bh] = tf32f(bv0[e]);
                b0p[(n2 * 4 + (bp ^ e)) * 2 + bh] = tf32f(bv1[e]);
            }
        }
        __syncthreads();

        if (k0 + 16 < K) {
            ra0 = *(const float4*)(Ap + (size_t)arow * K + k0 + 16 + acol);
            ra1 = *(const float4*)(Ap + (size_t)(arow + 64) * K + k0 + 16 + acol);
            rb0 = *(const float4*)(Bp + (size_t)(k0 + 16 + bkk) * N + bng * 8);
            rb1 = *(const float4*)(Bp + (size_t)(k0 + 16 + bkk) * N + bng * 8 + 4);
        }

#pragma unroll
        for (int kb = 0; kb < 2; kb++) {
            const float2* Ak = As[cur][kb];
            const float2* Bk = Bs[cur][kb];

            unsigned af[4][4];
#pragma unroll
            for (int mt = 0; mt < 4; mt++) {
                int row = wm + mt * 16 + fr;
                float2 lo = Ak[row * 4 + (fc ^ (row & 3))];
                float2 hi = Ak[(row + 8) * 4 + (fc ^ (row & 3))];
                af[mt][0] = __float_as_uint(lo.x);
                af[mt][1] = __float_as_uint(hi.x);
                af[mt][2] = __float_as_uint(lo.y);
                af[mt][3] = __float_as_uint(hi.y);
            }
            unsigned bf[4][2];
#pragma unroll
            for (int nt = 0; nt < 4; nt++) {
                int n = wn + nt * 8 + fr;
                float2 bb = Bk[n * 4 + (fc ^ (n & 3))];
                bf[nt][0] = __float_as_uint(bb.x);
                bf[nt][1] = __float_as_uint(bb.y);
            }
#pragma unroll
            for (int mt = 0; mt < 4; mt++)
#pragma unroll
                for (int nt = 0; nt < 4; nt++)
                    mma_tf32(acc[mt][nt], af[mt], bf[nt][0], bf[nt][1]);
        }
        cur ^= 1;
    }

#pragma unroll
    for (int mt = 0; mt < 4; mt++) {
#pragma unroll
        for (int nt = 0; nt < 4; nt++) {
            int row = bm + wm + mt * 16 + fr;
            int col = bn + wn + nt * 8 + 2 * fc;
            *(float2*)&C[(size_t)row * N + col] =
                make_float2(acc[mt][nt][0], acc[mt][nt][1]);
            *(float2*)&C[(size_t)(row + 8) * N + col] =
                make_float2(acc[mt][nt][2], acc[mt][nt][3]);
        }
    }
}

// ---------------------------------------------------------------------------
// Tensor-core block-diagonal attention v2 (tf32), flash-style online softmax.
// Block = 256 threads (8 warps), 128 queries of one (head, segment).
// Each warp owns 16 query rows -> softmax warp-local (shfl over fc only).
// K/V chunk loads amortized over 128 queries (2x v1). Dynamic smem 64KB:
//   Ks 8*256 f2 (16KB), Vs 8*256 f2 (16KB), Ps 8*512 f2 (32KB).
// __launch_bounds__(256,2): <=128 regs -> 2 CTAs/SM = 16 warps.
// ---------------------------------------------------------------------------
extern __shared__ float2 attn_smem[];

__global__ __launch_bounds__(256, 2)
void attn_tc(const float* __restrict__ qkv, float* __restrict__ y)
{
    float2* Ks = attn_smem;              // [kb][key*4 + (c ^ (key&3))]
    float2* Vs = attn_smem + 8 * 256;    // [kb][d*4   + (c ^ (d&3))]
    float2* Ps = attn_smem + 16 * 256;   // [kb][row*4 + (c ^ (row&3))], 128 rows

    const int tid  = threadIdx.x;
    const int lane = tid & 31;
    const int w    = tid >> 5;       // 0..7
    const int fr   = lane >> 2;      // 0..7
    const int fc   = lane & 3;       // 0..3
    const int h    = blockIdx.x & (H_HEADS - 1);
    const int seg  = blockIdx.x >> 4;
    const int q0   = seg * SEGLEN + blockIdx.y * 128;
    const int r0   = w * 16 + fr;    // warp-local q row (0..127); r0+8 for c2/c3
    const int sw   = fc ^ (fr & 3);

    const float* qb = qkv + (size_t)q0 * (3 * C_DIM) + h * HDIM;

    // ---- stage Q (scaled by 1/8, tf32) into Ps: 128 rows ----
    {
        const int row = tid >> 1;            // 0..127
        const int d0  = (tid & 1) * 32;
        const float* qr = qb + (size_t)row * (3 * C_DIM);
#pragma unroll
        for (int j = 0; j < 8; j++) {
            int d = d0 + j * 4;
            float4 v = *(const float4*)(qr + d);
            int kb = d >> 3;
            int cr = (d & 7) >> 1;           // 0 or 2
            Ps[kb * 512 + row * 4 + (cr ^ (row & 3))] =
                make_float2(tf32f(v.x * 0.125f), tf32f(v.y * 0.125f));
            Ps[kb * 512 + row * 4 + ((cr + 1) ^ (row & 3))] =
                make_float2(tf32f(v.z * 0.125f), tf32f(v.w * 0.125f));
        }
    }
    __syncthreads();

    // ---- Q fragments -> registers ----
    unsigned qf[8][4];
#pragma unroll
    for (int kb = 0; kb < 8; kb++) {
        float2 lo = Ps[kb * 512 + r0 * 4 + sw];
        float2 hi = Ps[kb * 512 + (r0 + 8) * 4 + sw];
        qf[kb][0] = __float_as_uint(lo.x);
        qf[kb][1] = __float_as_uint(hi.x);
        qf[kb][2] = __float_as_uint(lo.y);
        qf[kb][3] = __float_as_uint(hi.y);
    }

    float O[8][4];
#pragma unroll
    for (int nt = 0; nt < 8; nt++)
#pragma unroll
        for (int i = 0; i < 4; i++) O[nt][i] = 0.0f;
    float m0 = -1e30f, m1 = -1e30f, l0 = 0.0f, l1 = 0.0f;

    for (int kc = 0; kc < 8; kc++) {
        const float* kbase = qkv + (size_t)(seg * SEGLEN + kc * 64) * (3 * C_DIM)
                             + C_DIM + h * HDIM;
        const float* vbase = kbase + C_DIM;

        __syncthreads();   // all warps done reading Ks/Vs of previous chunk
        // ---- load K chunk: 64 keys x 64 d, 256 threads ----
        {
            const int key = tid >> 2;            // 0..63
            const int d0  = (tid & 3) * 16;
            const float* kr = kbase + (size_t)key * (3 * C_DIM);
#pragma unroll
            for (int j = 0; j < 4; j++) {
                int d = d0 + j * 4;
                float4 v = *(const float4*)(kr + d);
                int kb = d >> 3;
                int cr = (d & 7) >> 1;
                Ks[kb * 256 + key * 4 + (cr ^ (key & 3))] =
                    make_float2(tf32f(v.x), tf32f(v.y));
                Ks[kb * 256 + key * 4 + ((cr + 1) ^ (key & 3))] =
                    make_float2(tf32f(v.z), tf32f(v.w));
            }
        }
        // ---- load V chunk (key-pair-major transposed layout) ----
        {
            const int kp = tid >> 3;             // 0..31 -> keys 2kp, 2kp+1
            const int d0 = (tid & 7) * 8;
            const float* vr0 = vbase + (size_t)(2 * kp) * (3 * C_DIM);
            const float* vr1 = vr0 + (3 * C_DIM);
            const int kb = kp >> 2;
            const int cr = kp & 3;
#pragma unroll
            for (int j = 0; j < 2; j++) {
                int d = d0 + j * 4;
                float4 a = *(const float4*)(vr0 + d);
                float4 b = *(const float4*)(vr1 + d);
                Vs[kb * 256 + (d + 0) * 4 + (cr ^ ((d + 0) & 3))] = make_float2(tf32f(a.x), tf32f(b.x));
                Vs[kb * 256 + (d + 1) * 4 + (cr ^ ((d + 1) & 3))] = make_float2(tf32f(a.y), tf32f(b.y));
                Vs[kb * 256 + (d + 2) * 4 + (cr ^ ((d + 2) & 3))] = make_float2(tf32f(a.z), tf32f(b.z));
                Vs[kb * 256 + (d + 3) * 4 + (cr ^ ((d + 3) & 3))] = make_float2(tf32f(a.w), tf32f(b.w));
            }
        }
        __syncthreads();

        // ---- S = Q K^T (16 rows x 64 keys per warp) ----
        float s[8][4];
#pragma unroll
        for (int nt = 0; nt < 8; nt++)
#pragma unroll
            for (int i = 0; i < 4; i++) s[nt][i] = 0.0f;

#pragma unroll
        for (int kb = 0; kb < 8; kb++) {
#pragma unroll
            for (int nt = 0; nt < 8; nt++) {
                int n = nt * 8 + fr;
                float2 bb = Ks[kb * 256 + n * 4 + (fc ^ (n & 3))];
                mma_tf32(s[nt], qf[kb],
                         __float_as_uint(bb.x), __float_as_uint(bb.y));
            }
        }

        // ---- online softmax (warp-local rows r0, r0+8) ----
        float mx0 = -1e30f, mx1 = -1e30f;
#pragma unroll
        for (int nt = 0; nt < 8; nt++) {
            mx0 = fmaxf(mx0, fmaxf(s[nt][0], s[nt][1]));
            mx1 = fmaxf(mx1, fmaxf(s[nt][2], s[nt][3]));
        }
        mx0 = fmaxf(mx0, __shfl_xor_sync(0xffffffffu, mx0, 1));
        mx0 = fmaxf(mx0, __shfl_xor_sync(0xffffffffu, mx0, 2));
        mx1 = fmaxf(mx1, __shfl_xor_sync(0xffffffffu, mx1, 1));
        mx1 = fmaxf(mx1, __shfl_xor_sync(0xffffffffu, mx1, 2));

        float mn0 = fmaxf(m0, mx0), mn1 = fmaxf(m1, mx1);
        float fac0 = __expf(m0 - mn0), fac1 = __expf(m1 - mn1);
        float rs0 = 0.0f, rs1 = 0.0f;
#pragma unroll
        for (int nt = 0; nt < 8; nt++) {
            s[nt][0] = __expf(s[nt][0] - mn0);
            s[nt][1] = __expf(s[nt][1] - mn0);
            s[nt][2] = __expf(s[nt][2] - mn1);
            s[nt][3] = __expf(s[nt][3] - mn1);
            rs0 += s[nt][0] + s[nt][1];
            rs1 += s[nt][2] + s[nt][3];
        }
        rs0 += __shfl_xor_sync(0xffffffffu, rs0, 1);
        rs0 += __shfl_xor_sync(0xffffffffu, rs0, 2);
        rs1 += __shfl_xor_sync(0xffffffffu, rs1, 1);
        rs1 += __shfl_xor_sync(0xffffffffu, rs1, 2);

        l0 = l0 * fac0 + rs0;  m0 = mn0;
        l1 = l1 * fac1 + rs1;  m1 = mn1;
#pragma unroll
        for (int nt = 0; nt < 8; nt++) {
            O[nt][0] *= fac0; O[nt][1] *= fac0;
            O[nt][2] *= fac1; O[nt][3] *= fac1;
        }

        // ---- write P (warp-private rows; no sync needed) ----
#pragma unroll
        for (int nt = 0; nt < 8; nt++) {
            Ps[nt * 512 + r0 * 4 + sw]       = make_float2(tf32f(s[nt][0]), tf32f(s[nt][1]));
            Ps[nt * 512 + (r0 + 8) * 4 + sw] = make_float2(tf32f(s[nt][2]), tf32f(s[nt][3]));
        }

        // ---- O += P V ----
#pragma unroll
        for (int kb = 0; kb < 8; kb++) {
            float2 lo = Ps[kb * 512 + r0 * 4 + sw];
            float2 hi = Ps[kb * 512 + (r0 + 8) * 4 + sw];
            unsigned af[4] = {__float_as_uint(lo.x), __float_as_uint(hi.x),
                              __float_as_uint(lo.y), __float_as_uint(hi.y)};
#pragma unroll
            for (int nt = 0; nt < 8; nt++) {
                int n = nt * 8 + fr;
                float2 vv = Vs[kb * 256 + n * 4 + (fc ^ (n & 3))];
                mma_tf32(O[nt], af,
                         __float_as_uint(vv.x), __float_as_uint(vv.y));
            }
        }
    }

    // ---- epilogue: normalize, write y [T, C] ----
    const float inv0 = 1.0f / l0, inv1 = 1.0f / l1;
    float* yb = y + (size_t)q0 * C_DIM + h * HDIM;
#pragma unroll
    for (int nt = 0; nt < 8; nt++) {
        int col = nt * 8 + 2 * fc;
        *(float2*)&yb[(size_t)r0 * C_DIM + col] =
            make_float2(O[nt][0] * inv0, O[nt][1] * inv0);
        *(float2*)&yb[(size_t)(r0 + 8) * C_DIM + col] =
            make_float2(O[nt][2] * inv1, O[nt][3] * inv1);
    }
}

// ---------------------------------------------------------------------------
extern "C" void kernel_launch(void* const* d_in, const int* in_sizes, int n_in,
                              void* d_out, int out_size)
{
    const float* x      = (const float*)d_in[0];
    const float* w_attn = (const float*)d_in[1];
    const float* w_proj = (const float*)d_in[2];
    float* out = (float*)d_out;

    void* qkv_p = nullptr;
    void* y_p   = nullptr;
    cudaGetSymbolAddress(&qkv_p, g_qkv);
    cudaGetSymbolAddress(&y_p,   g_y);
    float* qkv = (float*)qkv_p;
    float* y   = (float*)y_p;

    const int ATTN_SMEM = 64 * 1024;   // 24*256 float2
    cudaFuncSetAttribute(attn_tc, cudaFuncAttributeMaxDynamicSharedMemorySize,
                         ATTN_SMEM);

    // 1) qkv = x @ w_attn   [16384,1024] x [1024,3072]
    gemm_tf32<<<dim3(3 * C_DIM / 128, T_TOK / 128), 256>>>(x, w_attn, qkv,
                                                           T_TOK, 3 * C_DIM, C_DIM);
    // 2) block-diagonal attention -> y [T, C]  (tensor cores, 8 warps/block)
    attn_tc<<<dim3(H_HEADS * NSEG, SEGLEN / 128), 256, ATTN_SMEM>>>(qkv, y);

    // 3) out = y @ w_proj   [16384,1024] x [1024,1024]
    gemm_tf32<<<dim3(C_DIM / 128, T_TOK / 128), 256>>>(y, w_proj, out,
                                                       T_TOK, C_DIM, C_DIM);
}

// round 10
// speedup vs baseline: 2.2804x; 1.1630x over previous
#include <cuda_runtime.h>
#include <cuda_fp16.h>
#include <math.h>

// Problem constants (fixed instance)
#define T_TOK   16384
#define C_DIM   1024
#define H_HEADS 16
#define HDIM    64
#define NSEG    32
#define SEGLEN  512

// Scratch (allocation-free: __device__ globals)
__device__ float g_qkv[(size_t)T_TOK * 3 * C_DIM];   // [T, 3C]
__device__ float g_y[(size_t)T_TOK * C_DIM];         // [T, C]

__device__ __forceinline__ unsigned h2u(float a, float b) {
    __half2 h = __floats2half2_rn(a, b);
    return *reinterpret_cast<unsigned*>(&h);
}

// D(fp32) += A(fp16) * B(fp16): m16n8k16, row.col
__device__ __forceinline__ void mma_f16(float* c, const unsigned* a,
                                        unsigned b0, unsigned b1) {
    asm volatile(
        "mma.sync.aligned.m16n8k16.row.col.f32.f16.f16.f32 "
        "{%0,%1,%2,%3}, {%4,%5,%6,%7}, {%8,%9}, {%0,%1,%2,%3};"
        : "+f"(c[0]), "+f"(c[1]), "+f"(c[2]), "+f"(c[3])
        : "r"(a[0]), "r"(a[1]), "r"(a[2]), "r"(a[3]), "r"(b0), "r"(b1));
}

// ---------------------------------------------------------------------------
// FP16 tensor-core GEMM: C[M,N] = A[M,K] * B[K,N], row-major fp32 in/out.
// 128x128 block tile, BK=16 (one k16 mma step/iter), 256 threads = 8 warps
// (2m x 4n), warp tile 64x32. Smem uint2 slot = k-quad (2c,2c+1 | 2c+8,2c+9),
// xor swizzle (c ^ (row&3)) -> conflict-free lds.64 fragment loads.
// Double buffered, 1 sync/iter. <=128 regs -> 2 CTAs/SM (16 warps).
// ---------------------------------------------------------------------------
#define GPAD 4
__global__ __launch_bounds__(256, 2)
void gemm_f16(const float* __restrict__ A, const float* __restrict__ B,
              float* __restrict__ C, int M, int N, int K)
{
    __shared__ uint2 As[2][512 + GPAD];   // [buf][m*4 + swz(c)]
    __shared__ uint2 Bs[2][512 + GPAD];   // [buf][n*4 + swz(c)]

    const int tid  = threadIdx.x;
    const int lane = tid & 31;
    const int w    = tid >> 5;
    const int wm   = (w >> 2) * 64;      // warp M offset (0 or 64)
    const int wn   = (w & 3) * 32;       // warp N offset
    const int bm   = blockIdx.y * 128;
    const int bn   = blockIdx.x * 128;

    // A: 128 rows x 16 k. arow = tid>>1, two float4 at cols acol, acol+4.
    const int arow = tid >> 1;            // 0..127
    const int acol = (tid & 1) * 8;       // 0 or 8
    // B: 16 k-rows x 128 n. Row pair (krow0, krow0+1), one float4 of n each.
    const int krow0 = (tid & 7) * 2;      // 0,2,..,14
    const int bn0   = (tid >> 3) * 4;     // 0..124

    const float* Ap = A + (size_t)bm * K;
    const float* Bp = B + bn;

    float acc[4][4][4];
#pragma unroll
    for (int mt = 0; mt < 4; mt++)
#pragma unroll
        for (int nt = 0; nt < 4; nt++)
#pragma unroll
            for (int i = 0; i < 4; i++) acc[mt][nt][i] = 0.0f;

    const int fr = lane >> 2;
    const int fc = lane & 3;

    // Prefetch first tile
    float4 ra0 = *(const float4*)(Ap + (size_t)arow * K + acol);
    float4 ra1 = *(const float4*)(Ap + (size_t)arow * K + acol + 4);
    float4 rb0 = *(const float4*)(Bp + (size_t)krow0 * N + bn0);
    float4 rb1 = *(const float4*)(Bp + (size_t)(krow0 + 1) * N + bn0);

    int cur = 0;
    for (int k0 = 0; k0 < K; k0 += 16) {
        // ---- store tile into smem[cur] (fp16, k-quad slots, swizzled) ----
        {
            // A: float4 at (arow, d0): halves (d0,d0+1)->slot c0, (d0+2,d0+3)->c0+1
#pragma unroll
            for (int j = 0; j < 2; j++) {
                float4 v = j ? ra1 : ra0;
                int d0 = acol + j * 4;              // 0,4,8,12
                int c0 = (d0 & 7) >> 1;             // 0 or 2
                int hi = d0 >> 3;                   // 0 or 1
                ((__half2*)&As[cur][arow * 4 + (c0 ^ (arow & 3))])[hi] =
                    __floats2half2_rn(v.x, v.y);
                ((__half2*)&As[cur][arow * 4 + ((c0 + 1) ^ (arow & 3))])[hi] =
                    __floats2half2_rn(v.z, v.w);
            }
            // B: rows krow0, krow0+1 -> half2 (k,k+1) per n
            {
                int c  = (krow0 & 7) >> 1;
                int hi = krow0 >> 3;
                float va[4] = {rb0.x, rb0.y, rb0.z, rb0.w};
                float vb[4] = {rb1.x, rb1.y, rb1.z, rb1.w};
#pragma unroll
                for (int e = 0; e < 4; e++) {
                    int n = bn0 + e;
                    ((__half2*)&Bs[cur][n * 4 + (c ^ (n & 3))])[hi] =
                        __floats2half2_rn(va[e], vb[e]);
                }
            }
        }
        __syncthreads();

        // ---- prefetch next tile ----
        if (k0 + 16 < K) {
            ra0 = *(const float4*)(Ap + (size_t)arow * K + k0 + 16 + acol);
            ra1 = *(const float4*)(Ap + (size_t)arow * K + k0 + 16 + acol + 4);
            rb0 = *(const float4*)(Bp + (size_t)(k0 + 16 + krow0) * N + bn0);
            rb1 = *(const float4*)(Bp + (size_t)(k0 + 17 + krow0) * N + bn0);
        }

        // ---- compute: one k16 step, 16 mma per warp ----
        {
            unsigned af[4][4];
#pragma unroll
            for (int mt = 0; mt < 4; mt++) {
                int row = wm + mt * 16 + fr;
                uint2 lo = As[cur][row * 4 + (fc ^ (row & 3))];
                uint2 hi = As[cur][(row + 8) * 4 + (fc ^ ((row + 8) & 3))];
                af[mt][0] = lo.x;   // (fr,   2fc..2fc+1)
                af[mt][1] = hi.x;   // (fr+8, 2fc..)
                af[mt][2] = lo.y;   // (fr,   2fc+8..)
                af[mt][3] = hi.y;   // (fr+8, 2fc+8..)
            }
            unsigned bf[4][2];
#pragma unroll
            for (int nt = 0; nt < 4; nt++) {
                int n = wn + nt * 8 + fr;
                uint2 bb = Bs[cur][n * 4 + (fc ^ (n & 3))];
                bf[nt][0] = bb.x;
                bf[nt][1] = bb.y;
            }
#pragma unroll
            for (int mt = 0; mt < 4; mt++)
#pragma unroll
                for (int nt = 0; nt < 4; nt++)
                    mma_f16(acc[mt][nt], af[mt], bf[nt][0], bf[nt][1]);
        }
        cur ^= 1;
    }

    // ---- epilogue ----
#pragma unroll
    for (int mt = 0; mt < 4; mt++) {
#pragma unroll
        for (int nt = 0; nt < 4; nt++) {
            int row = bm + wm + mt * 16 + fr;
            int col = bn + wn + nt * 8 + 2 * fc;
            *(float2*)&C[(size_t)row * N + col] =
                make_float2(acc[mt][nt][0], acc[mt][nt][1]);
            *(float2*)&C[(size_t)(row + 8) * N + col] =
                make_float2(acc[mt][nt][2], acc[mt][nt][3]);
        }
    }
}

// ---------------------------------------------------------------------------
// FP16 tensor-core block-diagonal attention, flash-style online softmax.
// Block = 256 threads (8 warps), 128 queries of one (head, segment).
// Each warp owns 16 query rows -> warp-local softmax (shfl over fc only).
// k16 alignment: S-accumulator cols (2fc,2fc+1) == A-operand k-slots, so P
// converts fp32->half2 IN REGISTERS (no smem round trip).
// Smem: 16KB pool (Q staging, then Ks 8KB + Vs 8KB). 2 CTAs/SM.
// ---------------------------------------------------------------------------
__global__ __launch_bounds__(256, 2)
void attn_f16(const float* __restrict__ qkv, float* __restrict__ y)
{
    __shared__ uint2 pool[2048];          // Qs overlays Ks+Vs
    uint2* Ks = pool;                     // [kb*256 + key*4 + swz]  (kb=0..3)
    uint2* Vs = pool + 1024;              // [kb*256 + d*4   + swz]

    const int tid  = threadIdx.x;
    const int lane = tid & 31;
    const int w    = tid >> 5;       // 0..7
    const int fr   = lane >> 2;      // 0..7
    const int fc   = lane & 3;       // 0..3
    const int h    = blockIdx.x & (H_HEADS - 1);
    const int seg  = blockIdx.x >> 4;
    const int q0   = seg * SEGLEN + blockIdx.y * 128;
    const int r0   = w * 16 + fr;    // warp q row (acc c0/c1); r0+8 for c2/c3

    const float* qb = qkv + (size_t)q0 * (3 * C_DIM) + h * HDIM;

    // ---- stage Q (scaled 1/8, fp16) into pool: 128 rows x 4 kb ----
    {
        const int row = tid >> 1;            // 0..127
        const int d0  = (tid & 1) * 32;
        const float* qr = qb + (size_t)row * (3 * C_DIM);
#pragma unroll
        for (int j = 0; j < 8; j++) {
            int d = d0 + j * 4;
            float4 v = *(const float4*)(qr + d);
            int kb = d >> 4;
            int kk = d & 15;
            int c0 = (kk & 7) >> 1;
            int hi = kk >> 3;
            ((__half2*)&pool[kb * 512 + row * 4 + (c0 ^ (row & 3))])[hi] =
                __floats2half2_rn(v.x * 0.125f, v.y * 0.125f);
            ((__half2*)&pool[kb * 512 + row * 4 + ((c0 + 1) ^ (row & 3))])[hi] =
                __floats2half2_rn(v.z * 0.125f, v.w * 0.125f);
        }
    }
    __syncthreads();

    // ---- Q fragments -> registers (held for whole kernel) ----
    unsigned qf[4][4];
#pragma unroll
    for (int kb = 0; kb < 4; kb++) {
        uint2 lo = pool[kb * 512 + r0 * 4 + (fc ^ (r0 & 3))];
        uint2 hi = pool[kb * 512 + (r0 + 8) * 4 + (fc ^ ((r0 + 8) & 3))];
        qf[kb][0] = lo.x;
        qf[kb][1] = hi.x;
        qf[kb][2] = lo.y;
        qf[kb][3] = hi.y;
    }

    float O[8][4];
#pragma unroll
    for (int nt = 0; nt < 8; nt++)
#pragma unroll
        for (int i = 0; i < 4; i++) O[nt][i] = 0.0f;
    float m0 = -1e30f, m1 = -1e30f, l0 = 0.0f, l1 = 0.0f;

    for (int kc = 0; kc < 8; kc++) {
        const float* kbase = qkv + (size_t)(seg * SEGLEN + kc * 64) * (3 * C_DIM)
                             + C_DIM + h * HDIM;
        const float* vbase = kbase + C_DIM;

        __syncthreads();   // prev chunk (or Q frags) fully consumed
        // ---- load K chunk: 64 keys x 64 d ----
        {
            const int key = tid >> 2;            // 0..63
            const int d0  = (tid & 3) * 16;
            const float* kr = kbase + (size_t)key * (3 * C_DIM);
#pragma unroll
            for (int j = 0; j < 4; j++) {
                int d = d0 + j * 4;
                float4 v = *(const float4*)(kr + d);
                int kb = d >> 4;
                int kk = d & 15;
                int c0 = (kk & 7) >> 1;
                int hi = kk >> 3;
                ((__half2*)&Ks[kb * 256 + key * 4 + (c0 ^ (key & 3))])[hi] =
                    __floats2half2_rn(v.x, v.y);
                ((__half2*)&Ks[kb * 256 + key * 4 + ((c0 + 1) ^ (key & 3))])[hi] =
                    __floats2half2_rn(v.z, v.w);
            }
        }
        // ---- load V chunk: key-pair half2 (key 2kp, 2kp+1) per d ----
        {
            const int kp = tid >> 3;             // 0..31
            const int d0 = (tid & 7) * 8;
            const float* vr0 = vbase + (size_t)(2 * kp) * (3 * C_DIM);
            const float* vr1 = vr0 + (3 * C_DIM);
            const int kb = kp >> 3;
            const int cp = kp & 7;
            const int c  = cp & 3;
            const int hi = cp >> 2;
#pragma unroll
            for (int j = 0; j < 2; j++) {
                int d = d0 + j * 4;
                float4 a = *(const float4*)(vr0 + d);
                float4 b = *(const float4*)(vr1 + d);
                float va[4] = {a.x, a.y, a.z, a.w};
                float vb[4] = {b.x, b.y, b.z, b.w};
#pragma unroll
                for (int e = 0; e < 4; e++) {
                    int dd = d + e;
                    ((__half2*)&Vs[kb * 256 + dd * 4 + (c ^ (dd & 3))])[hi] =
                        __floats2half2_rn(va[e], vb[e]);
                }
            }
        }
        __syncthreads();

        // ---- S = Q K^T (16 rows x 64 keys per warp), 32 mma ----
        float s[8][4];
#pragma unroll
        for (int nt = 0; nt < 8; nt++)
#pragma unroll
            for (int i = 0; i < 4; i++) s[nt][i] = 0.0f;

#pragma unroll
        for (int kb = 0; kb < 4; kb++) {
#pragma unroll
            for (int nt = 0; nt < 8; nt++) {
                int n = nt * 8 + fr;
                uint2 bb = Ks[kb * 256 + n * 4 + (fc ^ (n & 3))];
                mma_f16(s[nt], qf[kb], bb.x, bb.y);
            }
        }

        // ---- online softmax (warp-local rows r0, r0+8) ----
        float mx0 = -1e30f, mx1 = -1e30f;
#pragma unroll
        for (int nt = 0; nt < 8; nt++) {
            mx0 = fmaxf(mx0, fmaxf(s[nt][0], s[nt][1]));
            mx1 = fmaxf(mx1, fmaxf(s[nt][2], s[nt][3]));
        }
        mx0 = fmaxf(mx0, __shfl_xor_sync(0xffffffffu, mx0, 1));
        mx0 = fmaxf(mx0, __shfl_xor_sync(0xffffffffu, mx0, 2));
        mx1 = fmaxf(mx1, __shfl_xor_sync(0xffffffffu, mx1, 1));
        mx1 = fmaxf(mx1, __shfl_xor_sync(0xffffffffu, mx1, 2));

        float mn0 = fmaxf(m0, mx0), mn1 = fmaxf(m1, mx1);
        float fac0 = __expf(m0 - mn0), fac1 = __expf(m1 - mn1);
        float rs0 = 0.0f, rs1 = 0.0f;
#pragma unroll
        for (int nt = 0; nt < 8; nt++) {
            s[nt][0] = __expf(s[nt][0] - mn0);
            s[nt][1] = __expf(s[nt][1] - mn0);
            s[nt][2] = __expf(s[nt][2] - mn1);
            s[nt][3] = __expf(s[nt][3] - mn1);
            rs0 += s[nt][0] + s[nt][1];
            rs1 += s[nt][2] + s[nt][3];
        }
        rs0 += __shfl_xor_sync(0xffffffffu, rs0, 1);
        rs0 += __shfl_xor_sync(0xffffffffu, rs0, 2);
        rs1 += __shfl_xor_sync(0xffffffffu, rs1, 1);
        rs1 += __shfl_xor_sync(0xffffffffu, rs1, 2);

        l0 = l0 * fac0 + rs0;  m0 = mn0;
        l1 = l1 * fac1 + rs1;  m1 = mn1;
#pragma unroll
        for (int nt = 0; nt < 8; nt++) {
            O[nt][0] *= fac0; O[nt][1] *= fac0;
            O[nt][2] *= fac1; O[nt][3] *= fac1;
        }

        // ---- O += P V : P converted in registers (k16 frag == S frag) ----
#pragma unroll
        for (int kbp = 0; kbp < 4; kbp++) {
            unsigned af[4];
            af[0] = h2u(s[2 * kbp][0],     s[2 * kbp][1]);       // (r0,   k=2fc..)
            af[1] = h2u(s[2 * kbp][2],     s[2 * kbp][3]);       // (r0+8, k=2fc..)
            af[2] = h2u(s[2 * kbp + 1][0], s[2 * kbp + 1][1]);   // (r0,   k=2fc+8..)
            af[3] = h2u(s[2 * kbp + 1][2], s[2 * kbp + 1][3]);   // (r0+8, k=2fc+8..)
#pragma unroll
            for (int nt = 0; nt < 8; nt++) {
                int n = nt * 8 + fr;
                uint2 vv = Vs[kbp * 256 + n * 4 + (fc ^ (n & 3))];
                mma_f16(O[nt], af, vv.x, vv.y);
            }
        }
    }

    // ---- epilogue: normalize, write y [T, C] ----
    const float inv0 = 1.0f / l0, inv1 = 1.0f / l1;
    float* yb = y + (size_t)q0 * C_DIM + h * HDIM;
#pragma unroll
    for (int nt = 0; nt < 8; nt++) {
        int col = nt * 8 + 2 * fc;
        *(float2*)&yb[(size_t)r0 * C_DIM + col] =
            make_float2(O[nt][0] * inv0, O[nt][1] * inv0);
        *(float2*)&yb[(size_t)(r0 + 8) * C_DIM + col] =
            make_float2(O[nt][2] * inv1, O[nt][3] * inv1);
    }
}

// ---------------------------------------------------------------------------
extern "C" void kernel_launch(void* const* d_in, const int* in_sizes, int n_in,
                              void* d_out, int out_size)
{
    const float* x      = (const float*)d_in[0];
    const float* w_attn = (const float*)d_in[1];
    const float* w_proj = (const float*)d_in[2];
    float* out = (float*)d_out;

    void* qkv_p = nullptr;
    void* y_p   = nullptr;
    cudaGetSymbolAddress(&qkv_p, g_qkv);
    cudaGetSymbolAddress(&y_p,   g_y);
    float* qkv = (float*)qkv_p;
    float* y   = (float*)y_p;

    // 1) qkv = x @ w_attn   [16384,1024] x [1024,3072]  (fp16 tensor cores)
    gemm_f16<<<dim3(3 * C_DIM / 128, T_TOK / 128), 256>>>(x, w_attn, qkv,
                                                          T_TOK, 3 * C_DIM, C_DIM);
    // 2) block-diagonal attention -> y [T, C]  (fp16 tensor cores)
    attn_f16<<<dim3(H_HEADS * NSEG, SEGLEN / 128), 256>>>(qkv, y);

    // 3) out = y @ w_proj   [16384,1024] x [1024,1024]  (fp16 tensor cores)
    gemm_f16<<<dim3(C_DIM / 128, T_TOK / 128), 256>>>(y, w_proj, out,
                                                      T_TOK, C_DIM, C_DIM);
}

// round 16
// speedup vs baseline: 2.6859x; 1.1779x over previous
#include <cuda_runtime.h>
#include <cuda_fp16.h>
#include <cstdint>
#include <math.h>

// Problem constants (fixed instance)
#define T_TOK   16384
#define C_DIM   1024
#define H_HEADS 16
#define HDIM    64
#define NSEG    32
#define SEGLEN  512

// Scratch (allocation-free: __device__ globals)
__device__ __half g_xh[(size_t)T_TOK * C_DIM];          // x fp16
__device__ __half g_qkvh[(size_t)T_TOK * 3 * C_DIM];    // qkv fp16 [T][3C]
__device__ __half g_yh[(size_t)T_TOK * C_DIM];          // y fp16   [T][C]

__device__ __forceinline__ unsigned h2u(float a, float b) {
    __half2 h = __floats2half2_rn(a, b);
    return *reinterpret_cast<unsigned*>(&h);
}
// D(fp32) += A(fp16) * B(fp16): m16n8k16, row.col
__device__ __forceinline__ void mma_f16(float* c, const unsigned* a,
                                        unsigned b0, unsigned b1) {
    asm volatile(
        "mma.sync.aligned.m16n8k16.row.col.f32.f16.f16.f32 "
        "{%0,%1,%2,%3}, {%4,%5,%6,%7}, {%8,%9}, {%0,%1,%2,%3};"
        : "+f"(c[0]), "+f"(c[1]), "+f"(c[2]), "+f"(c[3])
        : "r"(a[0]), "r"(a[1]), "r"(a[2]), "r"(a[3]), "r"(b0), "r"(b1));
}

// ---------------------------------------------------------------------------
// x fp32 -> fp16
// ---------------------------------------------------------------------------
__global__ void conv_f2h(const float* __restrict__ x, __half* __restrict__ xh) {
    int i = (blockIdx.x * 256 + threadIdx.x) * 4;
    float4 v = *(const float4*)(x + i);
    __half2 a = __floats2half2_rn(v.x, v.y);
    __half2 b = __floats2half2_rn(v.z, v.w);
    *(uint2*)(xh + i) = make_uint2(*(unsigned*)&a, *(unsigned*)&b);
}

// ---------------------------------------------------------------------------
// FP16 tensor-core GEMM v2: C[M,N] = A[M,K](fp16) * B[K,N](fp32), row-major.
// 128x128 block tile, BK=32 (two k16 steps -> 32 mma per warp per sync),
// 256 threads = 8 warps (2m x 4n), warp tile 64x32.
// Smem uint2 slot = k-quad (2c,2c+1 | 2c+8,2c+9), swizzle c ^ (row&3)
// -> conflict-free lds.64 fragment loads. Double buffered, 1 sync/iter.
// ---------------------------------------------------------------------------
__global__ __launch_bounds__(256, 2)
void gemm_f16(const __half* __restrict__ A, const float* __restrict__ B,
              void* __restrict__ C, int M, int N, int K, int out_is_half)
{
    __shared__ uint2 As[2][2][516];   // [buf][kb][row*4 + swz(c)]
    __shared__ uint2 Bs[2][2][516];   // [buf][kb][n*4   + swz(c)]

    const int tid  = threadIdx.x;
    const int lane = tid & 31;
    const int w    = tid >> 5;
    const int wm   = (w >> 2) * 64;      // warp M offset (0 or 64)
    const int wn   = (w & 3) * 32;       // warp N offset
    const int bm   = blockIdx.y * 128;
    const int bn   = blockIdx.x * 128;

    // A (fp16): thread row = tid>>1, k-half a16 = (tid&1)*16 -> kb = tid&1
    const int arow = tid >> 1;           // 0..127
    const int akb  = tid & 1;            // k16 block
    // B (fp32): k-row pair kr0 = 2*(tid&15), n group n0 = (tid>>4)*8
    const int kr0  = (tid & 15) * 2;     // 0,2,..,30
    const int n0   = (tid >> 4) * 8;     // 0..120
    const int bkb  = kr0 >> 4;
    const int bp   = (kr0 >> 1) & 7;     // pair index in kb
    const int bc   = bp & 3;             // slot c
    const int bhi  = bp >> 2;            // uint half

    const __half* Ap = A + (size_t)bm * K;
    const float*  Bp = B + bn;

    float acc[4][4][4];
#pragma unroll
    for (int mt = 0; mt < 4; mt++)
#pragma unroll
        for (int nt = 0; nt < 4; nt++)
#pragma unroll
            for (int i = 0; i < 4; i++) acc[mt][nt][i] = 0.0f;

    const int fr = lane >> 2;
    const int fc = lane & 3;

    // Prefetch first chunk
    uint4  ra0 = *(const uint4*)(Ap + (size_t)arow * K + akb * 16);
    uint4  ra1 = *(const uint4*)(Ap + (size_t)arow * K + akb * 16 + 8);
    float4 rb0 = *(const float4*)(Bp + (size_t)kr0 * N + n0);
    float4 rb1 = *(const float4*)(Bp + (size_t)kr0 * N + n0 + 4);
    float4 rb2 = *(const float4*)(Bp + (size_t)(kr0 + 1) * N + n0);
    float4 rb3 = *(const float4*)(Bp + (size_t)(kr0 + 1) * N + n0 + 4);

    int cur = 0;
    for (int k0 = 0; k0 < K; k0 += 32) {
        // ---- store chunk into smem[cur] ----
        {
            // A: ra0 = halves k=0..7 of this kb (hi=0), ra1 = k=8..15 (hi=1)
            unsigned ha[4] = {ra0.x, ra0.y, ra0.z, ra0.w};
            unsigned hb[4] = {ra1.x, ra1.y, ra1.z, ra1.w};
#pragma unroll
            for (int e = 0; e < 4; e++) {
                unsigned* slot = (unsigned*)&As[cur][akb][arow * 4 + (e ^ (arow & 3))];
                slot[0] = ha[e];
                slot[1] = hb[e];
            }
            // B: pair rows (kr0, kr0+1) -> half2(k,k+1) per n
            float b0a[4] = {rb0.x, rb0.y, rb0.z, rb0.w};
            float b1a[4] = {rb2.x, rb2.y, rb2.z, rb2.w};
            float b0b[4] = {rb1.x, rb1.y, rb1.z, rb1.w};
            float b1b[4] = {rb3.x, rb3.y, rb3.z, rb3.w};
#pragma unroll
            for (int e = 0; e < 4; e++) {
                int n = n0 + e;
                ((unsigned*)&Bs[cur][bkb][n * 4 + (bc ^ (n & 3))])[bhi] =
                    h2u(b0a[e], b1a[e]);
            }
#pragma unroll
            for (int e = 0; e < 4; e++) {
                int n = n0 + 4 + e;
                ((unsigned*)&Bs[cur][bkb][n * 4 + (bc ^ (n & 3))])[bhi] =
                    h2u(b0b[e], b1b[e]);
            }
        }
        __syncthreads();

        // ---- prefetch next chunk ----
        if (k0 + 32 < K) {
            ra0 = *(const uint4*)(Ap + (size_t)arow * K + k0 + 32 + akb * 16);
            ra1 = *(const uint4*)(Ap + (size_t)arow * K + k0 + 32 + akb * 16 + 8);
            rb0 = *(const float4*)(Bp + (size_t)(k0 + 32 + kr0) * N + n0);
            rb1 = *(const float4*)(Bp + (size_t)(k0 + 32 + kr0) * N + n0 + 4);
            rb2 = *(const float4*)(Bp + (size_t)(k0 + 33 + kr0) * N + n0);
            rb3 = *(const float4*)(Bp + (size_t)(k0 + 33 + kr0) * N + n0 + 4);
        }

        // ---- compute: 2 k16 steps x 16 mma per warp ----
#pragma unroll
        for (int kb = 0; kb < 2; kb++) {
            unsigned af[4][4];
#pragma unroll
            for (int mt = 0; mt < 4; mt++) {
                int row = wm + mt * 16 + fr;
                uint2 lo = As[cur][kb][row * 4 + (fc ^ (row & 3))];
                uint2 hi = As[cur][kb][(row + 8) * 4 + (fc ^ ((row + 8) & 3))];
                af[mt][0] = lo.x;
                af[mt][1] = hi.x;
                af[mt][2] = lo.y;
                af[mt][3] = hi.y;
            }
            unsigned bf[4][2];
#pragma unroll
            for (int nt = 0; nt < 4; nt++) {
                int n = wn + nt * 8 + fr;
                uint2 bb = Bs[cur][kb][n * 4 + (fc ^ (n & 3))];
                bf[nt][0] = bb.x;
                bf[nt][1] = bb.y;
            }
#pragma unroll
            for (int mt = 0; mt < 4; mt++)
#pragma unroll
                for (int nt = 0; nt < 4; nt++)
                    mma_f16(acc[mt][nt], af[mt], bf[nt][0], bf[nt][1]);
        }
        __syncthreads();
        cur ^= 1;
    }

    // ---- epilogue ----
#pragma unroll
    for (int mt = 0; mt < 4; mt++) {
#pragma unroll
        for (int nt = 0; nt < 4; nt++) {
            int row = bm + wm + mt * 16 + fr;
            int col = bn + wn + nt * 8 + 2 * fc;
            if (out_is_half) {
                __half* Cp = (__half*)C;
                __half2 v0 = __floats2half2_rn(acc[mt][nt][0], acc[mt][nt][1]);
                __half2 v1 = __floats2half2_rn(acc[mt][nt][2], acc[mt][nt][3]);
                *(unsigned*)&Cp[(size_t)row * N + col]       = *(unsigned*)&v0;
                *(unsigned*)&Cp[(size_t)(row + 8) * N + col] = *(unsigned*)&v1;
            } else {
                float* Cp = (float*)C;
                *(float2*)&Cp[(size_t)row * N + col] =
                    make_float2(acc[mt][nt][0], acc[mt][nt][1]);
                *(float2*)&Cp[(size_t)(row + 8) * N + col] =
                    make_float2(acc[mt][nt][2], acc[mt][nt][3]);
            }
        }
    }
}

// ---------------------------------------------------------------------------
// FP16 mma.sync block-diagonal attention (proven R10 core, half in/out).
// Block = 256 threads (8 warps), 128 queries of one (head, segment).
// S scaled by 1/8 post-mma; P fed to PV mma from registers.
// ---------------------------------------------------------------------------
__global__ __launch_bounds__(256, 2)
void attn_f16(const __half* __restrict__ qkv, __half* __restrict__ y)
{
    __shared__ uint2 pool[2048];          // Qs overlays Ks+Vs
    uint2* Ks = pool;
    uint2* Vs = pool + 1024;

    const int tid  = threadIdx.x;
    const int lane = tid & 31;
    const int w    = tid >> 5;
    const int fr   = lane >> 2;
    const int fc   = lane & 3;
    const int h    = blockIdx.x & (H_HEADS - 1);
    const int seg  = blockIdx.x >> 4;
    const int q0   = seg * SEGLEN + blockIdx.y * 128;
    const int r0   = w * 16 + fr;

    const __half* qb = qkv + (size_t)q0 * (3 * C_DIM) + h * HDIM;

    // ---- stage Q into pool: 128 rows x 4 kb ----
    {
        const int row = tid >> 1;
        const int d0  = (tid & 1) * 32;
        const __half* qr = qb + (size_t)row * (3 * C_DIM);
#pragma unroll
        for (int j = 0; j < 8; j++) {
            int d = d0 + j * 4;
            uint2 raw = *(const uint2*)(qr + d);
            int kb = d >> 4;
            int kk = d & 15;
            int c0 = (kk & 7) >> 1;
            int hi = kk >> 3;
            ((unsigned*)&pool[kb * 512 + row * 4 + (c0 ^ (row & 3))])[hi] = raw.x;
            ((unsigned*)&pool[kb * 512 + row * 4 + ((c0 + 1) ^ (row & 3))])[hi] = raw.y;
        }
    }
    __syncthreads();

    unsigned qf[4][4];
#pragma unroll
    for (int kb = 0; kb < 4; kb++) {
        uint2 lo = pool[kb * 512 + r0 * 4 + (fc ^ (r0 & 3))];
        uint2 hi = pool[kb * 512 + (r0 + 8) * 4 + (fc ^ ((r0 + 8) & 3))];
        qf[kb][0] = lo.x;  qf[kb][1] = hi.x;  qf[kb][2] = lo.y;  qf[kb][3] = hi.y;
    }

    float O[8][4];
#pragma unroll
    for (int nt = 0; nt < 8; nt++)
#pragma unroll
        for (int i = 0; i < 4; i++) O[nt][i] = 0.0f;
    float m0 = -1e30f, m1 = -1e30f, l0 = 0.0f, l1 = 0.0f;

    for (int kc = 0; kc < 8; kc++) {
        const __half* kbase = qkv + (size_t)(seg * SEGLEN + kc * 64) * (3 * C_DIM)
                              + C_DIM + h * HDIM;
        const __half* vbase = kbase + C_DIM;

        __syncthreads();
        // ---- load K chunk ----
        {
            const int key = tid >> 2;
            const int d0  = (tid & 3) * 16;
            const __half* kr = kbase + (size_t)key * (3 * C_DIM);
#pragma unroll
            for (int j = 0; j < 4; j++) {
                int d = d0 + j * 4;
                uint2 raw = *(const uint2*)(kr + d);
                int kb = d >> 4;
                int kk = d & 15;
                int c0 = (kk & 7) >> 1;
                int hi = kk >> 3;
                ((unsigned*)&Ks[kb * 256 + key * 4 + (c0 ^ (key & 3))])[hi] = raw.x;
                ((unsigned*)&Ks[kb * 256 + key * 4 + ((c0 + 1) ^ (key & 3))])[hi] = raw.y;
            }
        }
        // ---- load V chunk (key-pair half2 per d) ----
        {
            const int kp = tid >> 3;
            const int d0 = (tid & 7) * 8;
            const __half* vr0 = vbase + (size_t)(2 * kp) * (3 * C_DIM);
            const __half* vr1 = vr0 + (3 * C_DIM);
            const int kb = kp >> 3;
            const int cp = kp & 7;
            const int c  = cp & 3;
            const int hi = cp >> 2;
#pragma unroll
            for (int j = 0; j < 2; j++) {
                int d = d0 + j * 4;
                uint2 ra = *(const uint2*)(vr0 + d);
                uint2 rb = *(const uint2*)(vr1 + d);
                __half2 a0 = *(__half2*)&ra.x, a1 = *(__half2*)&ra.y;
                __half2 b0 = *(__half2*)&rb.x, b1 = *(__half2*)&rb.y;
                __half2 p[4];
                p[0] = __halves2half2(__low2half(a0),  __low2half(b0));
                p[1] = __halves2half2(__high2half(a0), __high2half(b0));
                p[2] = __halves2half2(__low2half(a1),  __low2half(b1));
                p[3] = __halves2half2(__high2half(a1), __high2half(b1));
#pragma unroll
                for (int e = 0; e < 4; e++) {
                    int dd = d + e;
                    ((unsigned*)&Vs[kb * 256 + dd * 4 + (c ^ (dd & 3))])[hi] =
                        *(unsigned*)&p[e];
                }
            }
        }
        __syncthreads();

        // ---- S = Q K^T ----
        float s[8][4];
#pragma unroll
        for (int nt = 0; nt < 8; nt++)
#pragma unroll
            for (int i = 0; i < 4; i++) s[nt][i] = 0.0f;

#pragma unroll
        for (int kb = 0; kb < 4; kb++) {
#pragma unroll
            for (int nt = 0; nt < 8; nt++) {
                int n = nt * 8 + fr;
                uint2 bb = Ks[kb * 256 + n * 4 + (fc ^ (n & 3))];
                mma_f16(s[nt], qf[kb], bb.x, bb.y);
            }
        }
#pragma unroll
        for (int nt = 0; nt < 8; nt++)
#pragma unroll
            for (int i = 0; i < 4; i++) s[nt][i] *= 0.125f;

        // ---- online softmax (warp-local rows r0, r0+8) ----
        float mx0 = -1e30f, mx1 = -1e30f;
#pragma unroll
        for (int nt = 0; nt < 8; nt++) {
            mx0 = fmaxf(mx0, fmaxf(s[nt][0], s[nt][1]));
            mx1 = fmaxf(mx1, fmaxf(s[nt][2], s[nt][3]));
        }
        mx0 = fmaxf(mx0, __shfl_xor_sync(0xffffffffu, mx0, 1));
        mx0 = fmaxf(mx0, __shfl_xor_sync(0xffffffffu, mx0, 2));
        mx1 = fmaxf(mx1, __shfl_xor_sync(0xffffffffu, mx1, 1));
        mx1 = fmaxf(mx1, __shfl_xor_sync(0xffffffffu, mx1, 2));

        float mn0 = fmaxf(m0, mx0), mn1 = fmaxf(m1, mx1);
        float fac0 = __expf(m0 - mn0), fac1 = __expf(m1 - mn1);
        float rs0 = 0.0f, rs1 = 0.0f;
#pragma unroll
        for (int nt = 0; nt < 8; nt++) {
            s[nt][0] = __expf(s[nt][0] - mn0);
            s[nt][1] = __expf(s[nt][1] - mn0);
            s[nt][2] = __expf(s[nt][2] - mn1);
            s[nt][3] = __expf(s[nt][3] - mn1);
            rs0 += s[nt][0] + s[nt][1];
            rs1 += s[nt][2] + s[nt][3];
        }
        rs0 += __shfl_xor_sync(0xffffffffu, rs0, 1);
        rs0 += __shfl_xor_sync(0xffffffffu, rs0, 2);
        rs1 += __shfl_xor_sync(0xffffffffu, rs1, 1);
        rs1 += __shfl_xor_sync(0xffffffffu, rs1, 2);

        l0 = l0 * fac0 + rs0;  m0 = mn0;
        l1 = l1 * fac1 + rs1;  m1 = mn1;
#pragma unroll
        for (int nt = 0; nt < 8; nt++) {
            O[nt][0] *= fac0; O[nt][1] *= fac0;
            O[nt][2] *= fac1; O[nt][3] *= fac1;
        }

        // ---- O += P V (P built in registers) ----
#pragma unroll
        for (int kbp = 0; kbp < 4; kbp++) {
            unsigned af[4];
            af[0] = h2u(s[2 * kbp][0],     s[2 * kbp][1]);
            af[1] = h2u(s[2 * kbp][2],     s[2 * kbp][3]);
            af[2] = h2u(s[2 * kbp + 1][0], s[2 * kbp + 1][1]);
            af[3] = h2u(s[2 * kbp + 1][2], s[2 * kbp + 1][3]);
#pragma unroll
            for (int nt = 0; nt < 8; nt++) {
                int n = nt * 8 + fr;
                uint2 vv = Vs[kbp * 256 + n * 4 + (fc ^ (n & 3))];
                mma_f16(O[nt], af, vv.x, vv.y);
            }
        }
    }

    // ---- epilogue: normalize, write y fp16 [T, C] ----
    const float inv0 = 1.0f / l0, inv1 = 1.0f / l1;
    __half* yb = y + (size_t)q0 * C_DIM + h * HDIM;
#pragma unroll
    for (int nt = 0; nt < 8; nt++) {
        int col = nt * 8 + 2 * fc;
        __half2 o0 = __floats2half2_rn(O[nt][0] * inv0, O[nt][1] * inv0);
        __half2 o1 = __floats2half2_rn(O[nt][2] * inv1, O[nt][3] * inv1);
        *(unsigned*)&yb[(size_t)r0 * C_DIM + col]       = *(unsigned*)&o0;
        *(unsigned*)&yb[(size_t)(r0 + 8) * C_DIM + col] = *(unsigned*)&o1;
    }
}

// ---------------------------------------------------------------------------
extern "C" void kernel_launch(void* const* d_in, const int* in_sizes, int n_in,
                              void* d_out, int out_size)
{
    const float* x      = (const float*)d_in[0];
    const float* w_attn = (const float*)d_in[1];
    const float* w_proj = (const float*)d_in[2];
    float* out = (float*)d_out;

    void *xh_p, *qkvh_p, *yh_p;
    cudaGetSymbolAddress(&xh_p,   g_xh);
    cudaGetSymbolAddress(&qkvh_p, g_qkvh);
    cudaGetSymbolAddress(&yh_p,   g_yh);
    __half* xh   = (__half*)xh_p;
    __half* qkvh = (__half*)qkvh_p;
    __half* yh   = (__half*)yh_p;

    // 0) x -> fp16
    conv_f2h<<<(T_TOK * C_DIM) / 1024, 256>>>(x, xh);

    // 1) qkv(fp16) = x @ w_attn   [16384,1024] x [1024,3072]
    gemm_f16<<<dim3(3 * C_DIM / 128, T_TOK / 128), 256>>>(
        xh, w_attn, (void*)qkvh, T_TOK, 3 * C_DIM, C_DIM, 1);

    // 2) block-diagonal attention -> y fp16
    attn_f16<<<dim3(H_HEADS * NSEG, SEGLEN / 128), 256>>>(qkvh, yh);

    // 3) out(fp32) = y @ w_proj   [16384,1024] x [1024,1024]
    gemm_f16<<<dim3(C_DIM / 128, T_TOK / 128), 256>>>(
        yh, w_proj, (void*)out, T_TOK, C_DIM, C_DIM, 0);
}

// round 17
// speedup vs baseline: 3.1676x; 1.1793x over previous
#include <cuda_runtime.h>
#include <cuda_fp16.h>
#include <cstdint>
#include <math.h>

// Problem constants (fixed instance)
#define T_TOK   16384
#define C_DIM   1024
#define H_HEADS 16
#define HDIM    64
#define NSEG    32
#define SEGLEN  512

// Scratch (allocation-free: __device__ globals)
__device__ __half g_xh[(size_t)T_TOK * C_DIM];          // x fp16
__device__ __half g_wat[(size_t)3 * C_DIM * C_DIM];     // w_attn^T [3C][C] fp16
__device__ __half g_wpt[(size_t)C_DIM * C_DIM];         // w_proj^T [C][C] fp16
__device__ __half g_qkvh[(size_t)T_TOK * 3 * C_DIM];    // qkv fp16 [T][3C]
__device__ __half g_yh[(size_t)T_TOK * C_DIM];          // y fp16   [T][C]

__device__ __forceinline__ unsigned h2u(float a, float b) {
    __half2 h = __floats2half2_rn(a, b);
    return *reinterpret_cast<unsigned*>(&h);
}
// D(fp32) += A(fp16) * B(fp16): m16n8k16, row.col
__device__ __forceinline__ void mma_f16(float* c, const unsigned* a,
                                        unsigned b0, unsigned b1) {
    asm volatile(
        "mma.sync.aligned.m16n8k16.row.col.f32.f16.f16.f32 "
        "{%0,%1,%2,%3}, {%4,%5,%6,%7}, {%8,%9}, {%0,%1,%2,%3};"
        : "+f"(c[0]), "+f"(c[1]), "+f"(c[2]), "+f"(c[3])
        : "r"(a[0]), "r"(a[1]), "r"(a[2]), "r"(a[3]), "r"(b0), "r"(b1));
}

// ---------------------------------------------------------------------------
// x fp32 -> fp16
// ---------------------------------------------------------------------------
__global__ void conv_f2h(const float* __restrict__ x, __half* __restrict__ xh) {
    int i = (blockIdx.x * 256 + threadIdx.x) * 4;
    float4 v = *(const float4*)(x + i);
    __half2 a = __floats2half2_rn(v.x, v.y);
    __half2 b = __floats2half2_rn(v.z, v.w);
    *(uint2*)(xh + i) = make_uint2(*(unsigned*)&a, *(unsigned*)&b);
}

// W [K][N] fp32 -> Wt [N][K] fp16
__global__ void tconv(const float* __restrict__ W, __half* __restrict__ Wt,
                      int K, int N) {
    __shared__ float t[32][33];
    int n0 = blockIdx.x * 32, k0 = blockIdx.y * 32;
    int tx = threadIdx.x, ty = threadIdx.y;
#pragma unroll
    for (int j = 0; j < 4; j++)
        t[ty + 8 * j][tx] = W[(size_t)(k0 + ty + 8 * j) * N + n0 + tx];
    __syncthreads();
#pragma unroll
    for (int j = 0; j < 4; j++)
        Wt[(size_t)(n0 + ty + 8 * j) * K + k0 + tx] = __float2half(t[tx][ty + 8 * j]);
}

// ---------------------------------------------------------------------------
// FP16 tensor-core GEMM v3: C[M,N] = A[M,K] * Bt[N,K]^T, both fp16 K-major.
// 128x128 block tile, BK=32 (two k16 steps -> 32 mma per warp per sync),
// 256 threads = 8 warps (2m x 4n), warp tile 64x32.
// Symmetric staging: thread owns one row + one k16-half; 2 x uint4 LDG and
// 2 x st.128 STS per operand (slot swizzle folded into the pack). 1 sync/iter.
// Smem uint2 slot = k-quad (2c,2c+1 | 2c+8,2c+9), swizzle c ^ (row&3).
// ---------------------------------------------------------------------------
__global__ __launch_bounds__(256, 2)
void gemm_f16(const __half* __restrict__ A, const __half* __restrict__ Bt,
              void* __restrict__ C, int M, int N, int K, int out_is_half)
{
    __shared__ uint2 As[2][2][516];   // [buf][kb][row*4 + pos]
    __shared__ uint2 Bs[2][2][516];   // [buf][kb][n*4   + pos]

    const int tid  = threadIdx.x;
    const int lane = tid & 31;
    const int w    = tid >> 5;
    const int wm   = (w >> 2) * 64;      // warp M offset (0 or 64)
    const int wn   = (w & 3) * 32;       // warp N offset
    const int bm   = blockIdx.y * 128;
    const int bn   = blockIdx.x * 128;

    const int row = tid >> 1;            // 0..127 (tile row for A and Bt)
    const int kb  = tid & 1;             // k16 half of the BK=32 chunk
    const int sw  = row & 3;             // slot swizzle for this row

    const __half* Ap  = A  + (size_t)(bm + row) * K + kb * 16;
    const __half* Btp = Bt + (size_t)(bn + row) * K + kb * 16;

    float acc[4][4][4];
#pragma unroll
    for (int mt = 0; mt < 4; mt++)
#pragma unroll
        for (int nt = 0; nt < 4; nt++)
#pragma unroll
            for (int i = 0; i < 4; i++) acc[mt][nt][i] = 0.0f;

    const int fr = lane >> 2;
    const int fc = lane & 3;

    // Prefetch first chunk: k = kb*16 .. kb*16+15 of row
    uint4 ra0 = *(const uint4*)(Ap);       // halves k+0..7
    uint4 ra1 = *(const uint4*)(Ap + 8);   // halves k+8..15
    uint4 rb0 = *(const uint4*)(Btp);
    uint4 rb1 = *(const uint4*)(Btp + 8);

    int cur = 0;
    for (int k0 = 0; k0 < K; k0 += 32) {
        // ---- pack + store chunk into smem[cur] (2 x st.128 per operand) ----
        {
            // position p holds slot-content e = p ^ sw; slot e = (ha[e], hb[e])
            unsigned ha[4] = {ra0.x, ra0.y, ra0.z, ra0.w};
            unsigned hb[4] = {ra1.x, ra1.y, ra1.z, ra1.w};
            uint4 w0 = make_uint4(ha[0 ^ sw], hb[0 ^ sw], ha[1 ^ sw], hb[1 ^ sw]);
            uint4 w1 = make_uint4(ha[2 ^ sw], hb[2 ^ sw], ha[3 ^ sw], hb[3 ^ sw]);
            *(uint4*)&As[cur][kb][row * 4]     = w0;
            *(uint4*)&As[cur][kb][row * 4 + 2] = w1;

            unsigned hc[4] = {rb0.x, rb0.y, rb0.z, rb0.w};
            unsigned hd[4] = {rb1.x, rb1.y, rb1.z, rb1.w};
            uint4 w2 = make_uint4(hc[0 ^ sw], hd[0 ^ sw], hc[1 ^ sw], hd[1 ^ sw]);
            uint4 w3 = make_uint4(hc[2 ^ sw], hd[2 ^ sw], hc[3 ^ sw], hd[3 ^ sw]);
            *(uint4*)&Bs[cur][kb][row * 4]     = w2;
            *(uint4*)&Bs[cur][kb][row * 4 + 2] = w3;
        }
        __syncthreads();

        // ---- prefetch next chunk ----
        if (k0 + 32 < K) {
            ra0 = *(const uint4*)(Ap + k0 + 32);
            ra1 = *(const uint4*)(Ap + k0 + 40);
            rb0 = *(const uint4*)(Btp + k0 + 32);
            rb1 = *(const uint4*)(Btp + k0 + 40);
        }

        // ---- compute: 2 k16 steps x 16 mma per warp ----
#pragma unroll
        for (int kk = 0; kk < 2; kk++) {
            unsigned af[4][4];
#pragma unroll
            for (int mt = 0; mt < 4; mt++) {
                int r = wm + mt * 16 + fr;
                uint2 lo = As[cur][kk][r * 4 + (fc ^ (r & 3))];
                uint2 hi = As[cur][kk][(r + 8) * 4 + (fc ^ ((r + 8) & 3))];
                af[mt][0] = lo.x;
                af[mt][1] = hi.x;
                af[mt][2] = lo.y;
                af[mt][3] = hi.y;
            }
            unsigned bf[4][2];
#pragma unroll
            for (int nt = 0; nt < 4; nt++) {
                int n = wn + nt * 8 + fr;
                uint2 bb = Bs[cur][kk][n * 4 + (fc ^ (n & 3))];
                bf[nt][0] = bb.x;
                bf[nt][1] = bb.y;
            }
#pragma unroll
            for (int mt = 0; mt < 4; mt++)
#pragma unroll
                for (int nt = 0; nt < 4; nt++)
                    mma_f16(acc[mt][nt], af[mt], bf[nt][0], bf[nt][1]);
        }
        cur ^= 1;
    }

    // ---- epilogue ----
#pragma unroll
    for (int mt = 0; mt < 4; mt++) {
#pragma unroll
        for (int nt = 0; nt < 4; nt++) {
            int r   = bm + wm + mt * 16 + fr;
            int col = bn + wn + nt * 8 + 2 * fc;
            if (out_is_half) {
                __half* Cp = (__half*)C;
                __half2 v0 = __floats2half2_rn(acc[mt][nt][0], acc[mt][nt][1]);
                __half2 v1 = __floats2half2_rn(acc[mt][nt][2], acc[mt][nt][3]);
                *(unsigned*)&Cp[(size_t)r * N + col]       = *(unsigned*)&v0;
                *(unsigned*)&Cp[(size_t)(r + 8) * N + col] = *(unsigned*)&v1;
            } else {
                float* Cp = (float*)C;
                *(float2*)&Cp[(size_t)r * N + col] =
                    make_float2(acc[mt][nt][0], acc[mt][nt][1]);
                *(float2*)&Cp[(size_t)(r + 8) * N + col] =
                    make_float2(acc[mt][nt][2], acc[mt][nt][3]);
            }
        }
    }
}

// ---------------------------------------------------------------------------
// FP16 mma.sync block-diagonal attention (proven core, half in/out).
// Block = 256 threads (8 warps), 128 queries of one (head, segment).
// S scaled by 1/8 post-mma; P fed to PV mma from registers.
// ---------------------------------------------------------------------------
__global__ __launch_bounds__(256, 2)
void attn_f16(const __half* __restrict__ qkv, __half* __restrict__ y)
{
    __shared__ uint2 pool[2048];          // Qs overlays Ks+Vs
    uint2* Ks = pool;
    uint2* Vs = pool + 1024;

    const int tid  = threadIdx.x;
    const int lane = tid & 31;
    const int w    = tid >> 5;
    const int fr   = lane >> 2;
    const int fc   = lane & 3;
    const int h    = blockIdx.x & (H_HEADS - 1);
    const int seg  = blockIdx.x >> 4;
    const int q0   = seg * SEGLEN + blockIdx.y * 128;
    const int r0   = w * 16 + fr;

    const __half* qb = qkv + (size_t)q0 * (3 * C_DIM) + h * HDIM;

    // ---- stage Q into pool: 128 rows x 4 kb ----
    {
        const int row = tid >> 1;
        const int d0  = (tid & 1) * 32;
        const __half* qr = qb + (size_t)row * (3 * C_DIM);
#pragma unroll
        for (int j = 0; j < 8; j++) {
            int d = d0 + j * 4;
            uint2 raw = *(const uint2*)(qr + d);
            int kb = d >> 4;
            int kk = d & 15;
            int c0 = (kk & 7) >> 1;
            int hi = kk >> 3;
            ((unsigned*)&pool[kb * 512 + row * 4 + (c0 ^ (row & 3))])[hi] = raw.x;
            ((unsigned*)&pool[kb * 512 + row * 4 + ((c0 + 1) ^ (row & 3))])[hi] = raw.y;
        }
    }
    __syncthreads();

    unsigned qf[4][4];
#pragma unroll
    for (int kb = 0; kb < 4; kb++) {
        uint2 lo = pool[kb * 512 + r0 * 4 + (fc ^ (r0 & 3))];
        uint2 hi = pool[kb * 512 + (r0 + 8) * 4 + (fc ^ ((r0 + 8) & 3))];
        qf[kb][0] = lo.x;  qf[kb][1] = hi.x;  qf[kb][2] = lo.y;  qf[kb][3] = hi.y;
    }

    float O[8][4];
#pragma unroll
    for (int nt = 0; nt < 8; nt++)
#pragma unroll
        for (int i = 0; i < 4; i++) O[nt][i] = 0.0f;
    float m0 = -1e30f, m1 = -1e30f, l0 = 0.0f, l1 = 0.0f;

    for (int kc = 0; kc < 8; kc++) {
        const __half* kbase = qkv + (size_t)(seg * SEGLEN + kc * 64) * (3 * C_DIM)
                              + C_DIM + h * HDIM;
        const __half* vbase = kbase + C_DIM;

        __syncthreads();
        // ---- load K chunk ----
        {
            const int key = tid >> 2;
            const int d0  = (tid & 3) * 16;
            const __half* kr = kbase + (size_t)key * (3 * C_DIM);
#pragma unroll
            for (int j = 0; j < 4; j++) {
                int d = d0 + j * 4;
                uint2 raw = *(const uint2*)(kr + d);
                int kb = d >> 4;
                int kk = d & 15;
                int c0 = (kk & 7) >> 1;
                int hi = kk >> 3;
                ((unsigned*)&Ks[kb * 256 + key * 4 + (c0 ^ (key & 3))])[hi] = raw.x;
                ((unsigned*)&Ks[kb * 256 + key * 4 + ((c0 + 1) ^ (key & 3))])[hi] = raw.y;
            }
        }
        // ---- load V chunk (key-pair half2 per d) ----
        {
            const int kp = tid >> 3;
            const int d0 = (tid & 7) * 8;
            const __half* vr0 = vbase + (size_t)(2 * kp) * (3 * C_DIM);
            const __half* vr1 = vr0 + (3 * C_DIM);
            const int kb = kp >> 3;
            const int cp = kp & 7;
            const int c  = cp & 3;
            const int hi = cp >> 2;
#pragma unroll
            for (int j = 0; j < 2; j++) {
                int d = d0 + j * 4;
                uint2 ra = *(const uint2*)(vr0 + d);
                uint2 rb = *(const uint2*)(vr1 + d);
                __half2 a0 = *(__half2*)&ra.x, a1 = *(__half2*)&ra.y;
                __half2 b0 = *(__half2*)&rb.x, b1 = *(__half2*)&rb.y;
                __half2 p[4];
                p[0] = __halves2half2(__low2half(a0),  __low2half(b0));
                p[1] = __halves2half2(__high2half(a0), __high2half(b0));
                p[2] = __halves2half2(__low2half(a1),  __low2half(b1));
                p[3] = __halves2half2(__high2half(a1), __high2half(b1));
#pragma unroll
                for (int e = 0; e < 4; e++) {
                    int dd = d + e;
                    ((unsigned*)&Vs[kb * 256 + dd * 4 + (c ^ (dd & 3))])[hi] =
                        *(unsigned*)&p[e];
                }
            }
        }
        __syncthreads();

        // ---- S = Q K^T ----
        float s[8][4];
#pragma unroll
        for (int nt = 0; nt < 8; nt++)
#pragma unroll
            for (int i = 0; i < 4; i++) s[nt][i] = 0.0f;

#pragma unroll
        for (int kb = 0; kb < 4; kb++) {
#pragma unroll
            for (int nt = 0; nt < 8; nt++) {
                int n = nt * 8 + fr;
                uint2 bb = Ks[kb * 256 + n * 4 + (fc ^ (n & 3))];
                mma_f16(s[nt], qf[kb], bb.x, bb.y);
            }
        }
#pragma unroll
        for (int nt = 0; nt < 8; nt++)
#pragma unroll
            for (int i = 0; i < 4; i++) s[nt][i] *= 0.125f;

        // ---- online softmax (warp-local rows r0, r0+8) ----
        float mx0 = -1e30f, mx1 = -1e30f;
#pragma unroll
        for (int nt = 0; nt < 8; nt++) {
            mx0 = fmaxf(mx0, fmaxf(s[nt][0], s[nt][1]));
            mx1 = fmaxf(mx1, fmaxf(s[nt][2], s[nt][3]));
        }
        mx0 = fmaxf(mx0, __shfl_xor_sync(0xffffffffu, mx0, 1));
        mx0 = fmaxf(mx0, __shfl_xor_sync(0xffffffffu, mx0, 2));
        mx1 = fmaxf(mx1, __shfl_xor_sync(0xffffffffu, mx1, 1));
        mx1 = fmaxf(mx1, __shfl_xor_sync(0xffffffffu, mx1, 2));

        float mn0 = fmaxf(m0, mx0), mn1 = fmaxf(m1, mx1);
        float fac0 = __expf(m0 - mn0), fac1 = __expf(m1 - mn1);
        float rs0 = 0.0f, rs1 = 0.0f;
#pragma unroll
        for (int nt = 0; nt < 8; nt++) {
            s[nt][0] = __expf(s[nt][0] - mn0);
            s[nt][1] = __expf(s[nt][1] - mn0);
            s[nt][2] = __expf(s[nt][2] - mn1);
            s[nt][3] = __expf(s[nt][3] - mn1);
            rs0 += s[nt][0] + s[nt][1];
            rs1 += s[nt][2] + s[nt][3];
        }
        rs0 += __shfl_xor_sync(0xffffffffu, rs0, 1);
        rs0 += __shfl_xor_sync(0xffffffffu, rs0, 2);
        rs1 += __shfl_xor_sync(0xffffffffu, rs1, 1);
        rs1 += __shfl_xor_sync(0xffffffffu, rs1, 2);

        l0 = l0 * fac0 + rs0;  m0 = mn0;
        l1 = l1 * fac1 + rs1;  m1 = mn1;
#pragma unroll
        for (int nt = 0; nt < 8; nt++) {
            O[nt][0] *= fac0; O[nt][1] *= fac0;
            O[nt][2] *= fac1; O[nt][3] *= fac1;
        }

        // ---- O += P V (P built in registers) ----
#pragma unroll
        for (int kbp = 0; kbp < 4; kbp++) {
            unsigned af[4];
            af[0] = h2u(s[2 * kbp][0],     s[2 * kbp][1]);
            af[1] = h2u(s[2 * kbp][2],     s[2 * kbp][3]);
            af[2] = h2u(s[2 * kbp + 1][0], s[2 * kbp + 1][1]);
            af[3] = h2u(s[2 * kbp + 1][2], s[2 * kbp + 1][3]);
#pragma unroll
            for (int nt = 0; nt < 8; nt++) {
                int n = nt * 8 + fr;
                uint2 vv = Vs[kbp * 256 + n * 4 + (fc ^ (n & 3))];
                mma_f16(O[nt], af, vv.x, vv.y);
            }
        }
    }

    // ---- epilogue: normalize, write y fp16 [T, C] ----
    const float inv0 = 1.0f / l0, inv1 = 1.0f / l1;
    __half* yb = y + (size_t)q0 * C_DIM + h * HDIM;
#pragma unroll
    for (int nt = 0; nt < 8; nt++) {
        int col = nt * 8 + 2 * fc;
        __half2 o0 = __floats2half2_rn(O[nt][0] * inv0, O[nt][1] * inv0);
        __half2 o1 = __floats2half2_rn(O[nt][2] * inv1, O[nt][3] * inv1);
        *(unsigned*)&yb[(size_t)r0 * C_DIM + col]       = *(unsigned*)&o0;
        *(unsigned*)&yb[(size_t)(r0 + 8) * C_DIM + col] = *(unsigned*)&o1;
    }
}

// ---------------------------------------------------------------------------
extern "C" void kernel_launch(void* const* d_in, const int* in_sizes, int n_in,
                              void* d_out, int out_size)
{
    const float* x      = (const float*)d_in[0];
    const float* w_attn = (const float*)d_in[1];
    const float* w_proj = (const float*)d_in[2];
    float* out = (float*)d_out;

    void *xh_p, *wat_p, *wpt_p, *qkvh_p, *yh_p;
    cudaGetSymbolAddress(&xh_p,   g_xh);
    cudaGetSymbolAddress(&wat_p,  g_wat);
    cudaGetSymbolAddress(&wpt_p,  g_wpt);
    cudaGetSymbolAddress(&qkvh_p, g_qkvh);
    cudaGetSymbolAddress(&yh_p,   g_yh);
    __half* xh   = (__half*)xh_p;
    __half* wat  = (__half*)wat_p;
    __half* wpt  = (__half*)wpt_p;
    __half* qkvh = (__half*)qkvh_p;
    __half* yh   = (__half*)yh_p;

    // 0) conversions: x -> fp16; weights -> fp16 transposed [N][K]
    conv_f2h<<<(T_TOK * C_DIM) / 1024, 256>>>(x, xh);
    tconv<<<dim3(3 * C_DIM / 32, C_DIM / 32), dim3(32, 8)>>>(w_attn, wat,
                                                             C_DIM, 3 * C_DIM);
    tconv<<<dim3(C_DIM / 32, C_DIM / 32), dim3(32, 8)>>>(w_proj, wpt,
                                                         C_DIM, C_DIM);

    // 1) qkv(fp16) = x @ w_attn   [16384,1024] x [1024,3072]
    gemm_f16<<<dim3(3 * C_DIM / 128, T_TOK / 128), 256>>>(
        xh, wat, (void*)qkvh, T_TOK, 3 * C_DIM, C_DIM, 1);

    // 2) block-diagonal attention -> y fp16
    attn_f16<<<dim3(H_HEADS * NSEG, SEGLEN / 128), 256>>>(qkvh, yh);

    // 3) out(fp32) = y @ w_proj   [16384,1024] x [1024,1024]
    gemm_f16<<<dim3(C_DIM / 128, T_TOK / 128), 256>>>(
        yh, wpt, (void*)out, T_TOK, C_DIM, C_DIM, 0);
}